// round 10
// baseline (speedup 1.0000x reference)
#include <cuda_runtime.h>
#include <cstdint>

#define NUM_EMB 1024
#define EMB_DIM 64
#define NPIX    65536      // 64 * 32 * 32 pixels
#define NELEM   4194304    // 64 * 64 * 32 * 32
#define NBLK    256        // fused blocks (256 px each)
#define CAP     32         // candidate buffer per pixel
#define SA      9.0f                         // 2x quant scale (R5-validated)
#define SB      (127.0f * 1024.0f)           // code quant scale (R5-validated)
#define SASB    1170432.0f                   // SA*SB
#define DELTA_I 2928                         // 2.5e-3 * SASB + B-rounding slop

// ---------------- device scratch (no allocs allowed) ----------------
__device__ float    g_codeS[NUM_EMB];        // exact fp32 norms (rescore)
__device__ int      g_codeSI[NUM_EMB];       // int-scaled norms (screen)
__device__ int      g_counts[NUM_EMB];
__device__ double   g_part[NBLK];
__device__ int      g_ticket;
__device__ uint4    g_w8[NUM_EMB * 4];       // int8 codebook, 64B per code

// ---------------- helpers ----------------
static __device__ __forceinline__ int dp4a(int c, unsigned a, unsigned b) {
    int d;
    asm("dp4a.s32.s32 %0, %1, %2, %3;" : "=r"(d) : "r"(a), "r"(b), "r"(c));
    return d;
}
static __device__ __forceinline__ unsigned pack4s8(int v0, int v1, int v2, int v3) {
    return (unsigned)(v0 & 255) | ((unsigned)(v1 & 255) << 8)
         | ((unsigned)(v2 & 255) << 16) | ((unsigned)(v3 & 255) << 24);
}
static __device__ __forceinline__ int q8x(float v) {       // quantize 2x (clamped, R5)
    int r = __float2int_rn(v * SA);
    return max(-127, min(127, r));
}
static __device__ __forceinline__ uint32_t smem_u32(const void* p) {
    uint32_t a;
    asm("{ .reg .u64 t; cvta.to.shared.u64 t, %1; cvt.u32.u64 %0, t; }" : "=r"(a) : "l"(p));
    return a;
}
static __device__ __forceinline__ void cp16(uint32_t dst, const void* gsrc) {
    asm volatile("cp.async.cg.shared.global [%0], [%1], 16;"
                 :: "r"(dst), "l"(__cvta_generic_to_global(gsrc)) : "memory");
}
#define CP_COMMIT() asm volatile("cp.async.commit_group;" ::: "memory")
#define CP_WAIT0()  asm volatile("cp.async.wait_group 0;" ::: "memory")

// ---------------- kernel 1: staged prep — norms + int8 codebook ----------------
__global__ void __launch_bounds__(256) prep_kernel(const float* __restrict__ w) {
    __shared__ float se[64 * EMB_DIM];               // 16 KB: this block's codebook rows
    int tid = threadIdx.x;
    int k0  = blockIdx.x * 64;

    const float4* src = reinterpret_cast<const float4*>(w + k0 * EMB_DIM);
    float4*       dst = reinterpret_cast<float4*>(se);
    #pragma unroll
    for (int i = 0; i < 4; i++) dst[tid + 256 * i] = src[tid + 256 * i];
    __syncthreads();

    if (tid < 64) {                                  // exact code norms (validated order)
        const float* row = se + tid * EMB_DIM;
        float s = 0.0f;
        #pragma unroll
        for (int d = 0; d < EMB_DIM; d++)
            s = __fadd_rn(s, __fmul_rn(row[d], row[d]));
        g_codeS[k0 + tid]   = s;
        g_codeSI[k0 + tid]  = __float2int_rn(s * SASB);
        g_counts[k0 + tid]  = 0;
    }
    if (blockIdx.x == 0 && tid == 0) g_ticket = 0;

    // int8 pack: thread t -> code (t>>2), dims (t&3)*16 .. +15 (one uint4)
    int tl   = tid >> 2;
    int dbas = (tid & 3) * 16;
    const float* e = se + tl * EMB_DIM + dbas;
    unsigned wv[4];
    #pragma unroll
    for (int j = 0; j < 4; j++) {
        wv[j] = pack4s8(__float2int_rn(e[4 * j]     * SB),
                        __float2int_rn(e[4 * j + 1] * SB),
                        __float2int_rn(e[4 * j + 2] * SB),
                        __float2int_rn(e[4 * j + 3] * SB));
    }
    g_w8[(k0 + tl) * 4 + (tid & 3)] = make_uint4(wv[0], wv[1], wv[2], wv[3]);
}

// ---------------- kernel 2: fused dp4a screen + exact rescore + quantize + losses --------
__global__ void __launch_bounds__(256, 2) fused_kernel(const float* __restrict__ x,
                                                       const float* __restrict__ w,
                                                       float* __restrict__ out) {
    extern __shared__ char smem[];
    uint4*          sW    = reinterpret_cast<uint4*>(smem);             // 2 x 1024 (32 KB)
    int*            sBNi  = reinterpret_cast<int*>(smem + 32768);       // 1024 (4 KB)
    unsigned short* sCand = reinterpret_cast<unsigned short*>(smem + 36864);  // 256*CAP (16 KB)
    double*         sd    = reinterpret_cast<double*>(smem);            // alias sW (final)
    float*          sf    = reinterpret_cast<float*>(smem + 2048);      // alias sW (final)
    __shared__ bool isLast;

    int tid = threadIdx.x;
    int p   = blockIdx.x * 256 + tid;                 // this thread's pixel
    int b   = p >> 10;
    int hw  = p & 1023;
    const float* xp = x + (size_t)b * 65536 + hw;     // NCHW, dim stride 1024

    // ---------------- phase A: int8 dp4a screen ----------------
    uint32_t sw0 = smem_u32(sW);
    uint32_t sw1 = smem_u32(sW + 1024);
    #pragma unroll
    for (int i = 0; i < 4; i++) cp16(sw0 + (tid + 256 * i) * 16, &g_w8[tid + 256 * i]);
    CP_COMMIT();

    #pragma unroll
    for (int i = 0; i < 4; i++) sBNi[tid + 256 * i] = g_codeSI[tid + 256 * i];

    unsigned xq[16];                                  // quantized 2x, 4 dims per word
    #pragma unroll
    for (int j = 0; j < 16; j++) {
        xq[j] = pack4s8(q8x(2.0f * xp[(size_t)(4 * j)     * 1024]),
                        q8x(2.0f * xp[(size_t)(4 * j + 1) * 1024]),
                        q8x(2.0f * xp[(size_t)(4 * j + 2) * 1024]),
                        q8x(2.0f * xp[(size_t)(4 * j + 3) * 1024]));
    }

    int besti = 0x7FFFFFFF;
    int cnt   = 0;

    for (int s = 0; s < 4; s++) {                     // 4 chunks of 256 codes
        CP_WAIT0();
        __syncthreads();
        if (s < 3) {
            uint32_t db = ((s + 1) & 1) ? sw1 : sw0;
            const uint4* gsrc = g_w8 + (s + 1) * 1024;
            #pragma unroll
            for (int i = 0; i < 4; i++) cp16(db + (tid + 256 * i) * 16, gsrc + tid + 256 * i);
            CP_COMMIT();
        }
        const uint4* cw = sW + (s & 1) * 1024;
        const int*   bn = sBNi + s * 256;

        for (int kk = 0; kk < 256; kk += 2) {         // 2 codes per iter, 4 dp4a chains
            uint4 a0 = cw[kk * 4 + 0], a1 = cw[kk * 4 + 1];
            uint4 a2 = cw[kk * 4 + 2], a3 = cw[kk * 4 + 3];
            uint4 b0 = cw[kk * 4 + 4], b1 = cw[kk * 4 + 5];
            uint4 b2 = cw[kk * 4 + 6], b3 = cw[kk * 4 + 7];

            int ca = 0, cb = 0, cc = 0, cd = 0;
            ca = dp4a(ca, xq[0],  a0.x); cc = dp4a(cc, xq[0],  b0.x);
            ca = dp4a(ca, xq[1],  a0.y); cc = dp4a(cc, xq[1],  b0.y);
            ca = dp4a(ca, xq[2],  a0.z); cc = dp4a(cc, xq[2],  b0.z);
            ca = dp4a(ca, xq[3],  a0.w); cc = dp4a(cc, xq[3],  b0.w);
            ca = dp4a(ca, xq[4],  a1.x); cc = dp4a(cc, xq[4],  b1.x);
            ca = dp4a(ca, xq[5],  a1.y); cc = dp4a(cc, xq[5],  b1.y);
            ca = dp4a(ca, xq[6],  a1.z); cc = dp4a(cc, xq[6],  b1.z);
            ca = dp4a(ca, xq[7],  a1.w); cc = dp4a(cc, xq[7],  b1.w);
            cb = dp4a(cb, xq[8],  a2.x); cd = dp4a(cd, xq[8],  b2.x);
            cb = dp4a(cb, xq[9],  a2.y); cd = dp4a(cd, xq[9],  b2.y);
            cb = dp4a(cb, xq[10], a2.z); cd = dp4a(cd, xq[10], b2.z);
            cb = dp4a(cb, xq[11], a2.w); cd = dp4a(cd, xq[11], b2.w);
            cb = dp4a(cb, xq[12], a3.x); cd = dp4a(cd, xq[12], b3.x);
            cb = dp4a(cb, xq[13], a3.y); cd = dp4a(cd, xq[13], b3.y);
            cb = dp4a(cb, xq[14], a3.z); cd = dp4a(cd, xq[14], b3.z);
            cb = dp4a(cb, xq[15], a3.w); cd = dp4a(cd, xq[15], b3.w);

            int d0 = bn[kk]     - (ca + cb);          // screen dist, int domain
            int d1 = bn[kk + 1] - (cc + cd);

            besti = min(besti, min(d0, d1));
            int thr = besti + DELTA_I;
            if (d0 < thr) { if (cnt < CAP) sCand[tid * CAP + cnt] = (unsigned short)(s * 256 + kk); cnt++; }
            if (d1 < thr) { if (cnt < CAP) sCand[tid * CAP + cnt] = (unsigned short)(s * 256 + kk + 1); cnt++; }
        }
        __syncthreads();
    }

    // ---------------- phase B: exact rescore + quantize + STE + loss partial ----------------
    double acc = 0.0;
    {
        float xv[EMB_DIM];
        float A = 0.0f;
        #pragma unroll
        for (int d = 0; d < EMB_DIM; d++) {
            float v = xp[(size_t)d * 1024];
            xv[d] = v;
            A = __fadd_rn(A, __fmul_rn(v, v));
        }

        float bd = 3.4e38f;
        int   bi = 0;

        if (cnt > CAP) {                              // overflow: exact full scan
            for (int k = 0; k < NUM_EMB; k++) {
                const float* e = w + k * EMB_DIM;
                float m = 0.0f;
                #pragma unroll
                for (int d = 0; d < EMB_DIM; d++) m = __fmaf_rn(xv[d], e[d], m);
                float dist = __fsub_rn(__fadd_rn(A, g_codeS[k]), 2.0f * m);
                if (dist < bd) { bd = dist; bi = k; }
            }
        } else {
            for (int j = 0; j < cnt; j++) {
                int k = sCand[tid * CAP + j];
                const float4* e4 = reinterpret_cast<const float4*>(w + k * EMB_DIM);
                float m = 0.0f;
                #pragma unroll
                for (int d4 = 0; d4 < 16; d4++) {
                    float4 ev = e4[d4];
                    m = __fmaf_rn(xv[4 * d4],     ev.x, m);
                    m = __fmaf_rn(xv[4 * d4 + 1], ev.y, m);
                    m = __fmaf_rn(xv[4 * d4 + 2], ev.z, m);
                    m = __fmaf_rn(xv[4 * d4 + 3], ev.w, m);
                }
                float dist = __fsub_rn(__fadd_rn(A, g_codeS[k]), 2.0f * m);
                if (dist < bd || (dist == bd && k < bi)) { bd = dist; bi = k; }
            }
        }

        out[NELEM + 2 + p] = (float)bi;               // idx output
        atomicAdd(&g_counts[bi], 1);

        const float4* wr = reinterpret_cast<const float4*>(w + bi * EMB_DIM);
        float* ob = out + (size_t)b * 65536 + hw;
        #pragma unroll
        for (int j = 0; j < 16; j++) {
            float4 qv = wr[j];
            float x0 = xv[4 * j], x1 = xv[4 * j + 1], x2 = xv[4 * j + 2], x3 = xv[4 * j + 3];
            float d0 = __fsub_rn(qv.x, x0), d1 = __fsub_rn(qv.y, x1);
            float d2 = __fsub_rn(qv.z, x2), d3 = __fsub_rn(qv.w, x3);
            ob[(size_t)(4 * j)     * 1024] = __fadd_rn(x0, d0);
            ob[(size_t)(4 * j + 1) * 1024] = __fadd_rn(x1, d1);
            ob[(size_t)(4 * j + 2) * 1024] = __fadd_rn(x2, d2);
            ob[(size_t)(4 * j + 3) * 1024] = __fadd_rn(x3, d3);
            acc += (double)d0 * d0 + (double)d1 * d1 + (double)d2 * d2 + (double)d3 * d3;
        }
    }
    __syncthreads();                                  // sW reads done before sd alias

    sd[tid] = acc;
    __syncthreads();
    #pragma unroll
    for (int s = 128; s > 0; s >>= 1) {
        if (tid < s) sd[tid] += sd[tid + s];
        __syncthreads();
    }
    if (tid == 0) g_part[blockIdx.x] = sd[0];
    __threadfence();
    if (tid == 0) isLast = (atomicAdd(&g_ticket, 1) == NBLK - 1);
    __syncthreads();

    if (isLast) {                                     // deterministic final reduction
        __threadfence();
        sd[tid] = g_part[tid];

        float f = 0.0f;
        #pragma unroll
        for (int i = 0; i < NUM_EMB / 256; i++) {
            float pr = (float)g_counts[tid * (NUM_EMB / 256) + i] * (1.0f / 65536.0f);
            f += pr * logf(pr + 1e-10f);
        }
        sf[tid] = f;
        __syncthreads();
        #pragma unroll
        for (int st = 128; st > 0; st >>= 1) {
            if (tid < st) { sd[tid] += sd[tid + st]; sf[tid] += sf[tid + st]; }
            __syncthreads();
        }
        if (tid == 0) {
            float m = (float)(sd[0] / (double)NELEM);
            out[NELEM]     = __fadd_rn(m, __fmul_rn(0.25f, m));  // q_loss + 0.25*e_loss
            out[NELEM + 1] = expf(-sf[0]);
        }
    }
}

extern "C" void kernel_launch(void* const* d_in, const int* in_sizes, int n_in,
                              void* d_out, int out_size) {
    const float* x;
    const float* w;
    if (in_sizes[0] == NELEM) { x = (const float*)d_in[0]; w = (const float*)d_in[1]; }
    else                      { x = (const float*)d_in[1]; w = (const float*)d_in[0]; }
    float* out = (float*)d_out;

    cudaFuncSetAttribute(fused_kernel, cudaFuncAttributeMaxDynamicSharedMemorySize, 53248);

    prep_kernel<<<16, 256>>>(w);
    fused_kernel<<<NBLK, 256, 53248>>>(x, w, out);
}

// round 11
// speedup vs baseline: 1.3775x; 1.3775x over previous
#include <cuda_runtime.h>
#include <cuda_bf16.h>
#include <cstdint>

#define NUM_EMB 1024
#define EMB_DIM 64
#define NPIX    65536      // 64 * 32 * 32 pixels
#define NELEM   4194304    // 64 * 64 * 32 * 32
#define NBLK    512        // fused-kernel blocks (128 px each)
#define CAP     32         // candidate buffer per pixel
#define DELTA   2e-3f      // screen window >= 2*max_bf16_err + grid slop

// ---------------- device scratch (no allocs allowed) ----------------
__device__ float    g_codeS[NUM_EMB];
__device__ int      g_counts[NUM_EMB];
__device__ double   g_part[NBLK];
__device__ int      g_ticket;
__device__ uint4    g_bfrag[128 * 64];            // [tile][2 groups x 32 lanes] bf16-hi fragments

// ---------------- helpers ----------------
static __device__ __forceinline__ uint32_t packbf(float a, float b) {
    uint16_t ha = __bfloat16_as_ushort(__float2bfloat16_rn(a));
    uint16_t hb = __bfloat16_as_ushort(__float2bfloat16_rn(b));
    return (uint32_t)ha | ((uint32_t)hb << 16);
}
static __device__ __forceinline__ void mma16816(float& c0, float& c1, float& c2, float& c3,
                                                uint32_t a0, uint32_t a1, uint32_t a2, uint32_t a3,
                                                uint32_t b0, uint32_t b1) {
    asm volatile("mma.sync.aligned.m16n8k16.row.col.f32.bf16.bf16.f32 "
                 "{%0,%1,%2,%3}, {%4,%5,%6,%7}, {%8,%9}, {%0,%1,%2,%3};"
                 : "+f"(c0), "+f"(c1), "+f"(c2), "+f"(c3)
                 : "r"(a0), "r"(a1), "r"(a2), "r"(a3), "r"(b0), "r"(b1));
}
static __device__ __forceinline__ uint32_t smem_u32(const void* p) {
    uint32_t a;
    asm("{ .reg .u64 t; cvta.to.shared.u64 t, %1; cvt.u32.u64 %0, t; }" : "=r"(a) : "l"(p));
    return a;
}
static __device__ __forceinline__ void cp16(uint32_t dst, const void* gsrc) {
    asm volatile("cp.async.cg.shared.global [%0], [%1], 16;"
                 :: "r"(dst), "l"(__cvta_generic_to_global(gsrc)) : "memory");
}
#define CP_COMMIT() asm volatile("cp.async.commit_group;" ::: "memory")
#define CP_WAIT0()  asm volatile("cp.async.wait_group 0;" ::: "memory")

// ---------------- kernel 1: staged prep — norms + bf16-hi fragments ----------------
__global__ void __launch_bounds__(256) prep_kernel(const float* __restrict__ w) {
    __shared__ float se[64 * EMB_DIM];               // 16 KB: this block's codebook rows
    int tid = threadIdx.x;
    int k0  = blockIdx.x * 64;

    const float4* src = reinterpret_cast<const float4*>(w + k0 * EMB_DIM);
    float4*       dst = reinterpret_cast<float4*>(se);
    #pragma unroll
    for (int i = 0; i < 4; i++) dst[tid + 256 * i] = src[tid + 256 * i];
    __syncthreads();

    if (tid < 64) {                                  // exact code norms (validated order)
        const float* row = se + tid * EMB_DIM;
        float s = 0.0f;
        #pragma unroll
        for (int d = 0; d < EMB_DIM; d++)
            s = __fadd_rn(s, __fmul_rn(row[d], row[d]));
        g_codeS[k0 + tid]  = s;
        g_counts[k0 + tid] = 0;
    }
    if (blockIdx.x == 0 && tid == 0) g_ticket = 0;

    int tl   = tid >> 5;
    int lane = tid & 31;
    int tile = blockIdx.x * 8 + tl;
    int q    = lane & 3;
    const float* e = se + (tl * 8 + (lane >> 2)) * EMB_DIM;

    uint32_t hiw[8];
    #pragma unroll
    for (int s = 0; s < 4; s++) {
        int ks = 16 * s + 2 * q;
        hiw[2 * s]     = packbf(e[ks],     e[ks + 1]);
        hiw[2 * s + 1] = packbf(e[ks + 8], e[ks + 9]);
    }
    g_bfrag[tile * 64 +      lane] = make_uint4(hiw[0], hiw[1], hiw[2], hiw[3]);
    g_bfrag[tile * 64 + 32 + lane] = make_uint4(hiw[4], hiw[5], hiw[6], hiw[7]);
}

// ---------------- kernel 2: fused screen + exact rescore + quantize + losses ----------------
__global__ void __launch_bounds__(256, 2) fused_kernel(const float* __restrict__ x,
                                                       const float* __restrict__ w,
                                                       float* __restrict__ out) {
    __shared__ float sBN[NUM_EMB];                   // 4 KB
    __shared__ uint4 sB[2][1024];                    // 32 KB, aliased by sd/sf in final
    __shared__ unsigned short sCand[128 * CAP];      // 8 KB
    __shared__ int   sCnt[128];                      // 0.5 KB
    __shared__ float sBd[128];                       // phase-B combine
    __shared__ int   sBi[128];
    __shared__ bool  isLast;

    double* sd = reinterpret_cast<double*>(&sB[0][0]);         // 256 * 8B
    float*  sf = reinterpret_cast<float*>(&sB[0][0]) + 512;    // 256 * 4B

    int tid  = threadIdx.x;
    int warp = tid >> 5;
    int lane = tid & 31;
    int q    = lane & 3;
    int r    = lane >> 2;
    int p0b  = blockIdx.x * 128;

    // ---------------- phase A: HMMA bf16 screen (R7-identical MMA math) ----------------
    uint32_t sb0 = smem_u32(&sB[0][0]);
    uint32_t sb1 = smem_u32(&sB[1][0]);
    #pragma unroll
    for (int i = 0; i < 4; i++) cp16(sb0 + (tid + 256 * i) * 16, &g_bfrag[tid + 256 * i]);
    CP_COMMIT();

    #pragma unroll
    for (int i = 0; i < 4; i++) sBN[tid + 256 * i] = g_codeS[tid + 256 * i];
    if (tid < 128) sCnt[tid] = 0;

    int p0 = p0b + warp * 16;
    const float* xb = x + (size_t)(p0 >> 10) * 65536 + (p0 & 1023);  // NCHW, dim stride 1024

    uint32_t Ahi[16];
    #pragma unroll
    for (int s = 0; s < 4; s++) {
        int k0 = 16 * s + 2 * q;
        float p00 = 2.0f * xb[(size_t)k0 * 1024 + r];
        float p01 = 2.0f * xb[(size_t)(k0 + 1) * 1024 + r];
        float p10 = 2.0f * xb[(size_t)k0 * 1024 + r + 8];
        float p11 = 2.0f * xb[(size_t)(k0 + 1) * 1024 + r + 8];
        float p20 = 2.0f * xb[(size_t)(k0 + 8) * 1024 + r];
        float p21 = 2.0f * xb[(size_t)(k0 + 9) * 1024 + r];
        float p30 = 2.0f * xb[(size_t)(k0 + 8) * 1024 + r + 8];
        float p31 = 2.0f * xb[(size_t)(k0 + 9) * 1024 + r + 8];
        Ahi[s * 4 + 0] = packbf(p00, p01);
        Ahi[s * 4 + 1] = packbf(p10, p11);
        Ahi[s * 4 + 2] = packbf(p20, p21);
        Ahi[s * 4 + 3] = packbf(p30, p31);
    }

    float bestL = 3.4e38f, bestH = 3.4e38f;
    int lpL = warp * 16 + r;                          // local pixel ids
    int lpH = lpL + 8;

    for (int s = 0; s < 8; s++) {
        CP_WAIT0();
        __syncthreads();
        if (s < 7) {
            uint32_t db = ((s + 1) & 1) ? sb1 : sb0;
            const uint4* gsrc = g_bfrag + (s + 1) * 1024;
            #pragma unroll
            for (int i = 0; i < 4; i++) cp16(db + (tid + 256 * i) * 16, gsrc + tid + 256 * i);
            CP_COMMIT();
        }
        const uint4* cur = sB[s & 1];

        #pragma unroll
        for (int g = 0; g < 4; g++) {                 // 4 tiles per group
            float dL[8], dH[8];
            #pragma unroll
            for (int tt = 0; tt < 4; tt++) {
                int tile = s * 16 + g * 4 + tt;
                int tloc = (g * 4 + tt) * 64;
                uint4 f0 = cur[tloc + lane];
                uint4 f1 = cur[tloc + 32 + lane];

                float c0 = 0.f, c1 = 0.f, c2 = 0.f, c3 = 0.f;
                mma16816(c0, c1, c2, c3, Ahi[0],  Ahi[1],  Ahi[2],  Ahi[3],  f0.x, f0.y);
                mma16816(c0, c1, c2, c3, Ahi[4],  Ahi[5],  Ahi[6],  Ahi[7],  f0.z, f0.w);
                mma16816(c0, c1, c2, c3, Ahi[8],  Ahi[9],  Ahi[10], Ahi[11], f1.x, f1.y);
                mma16816(c0, c1, c2, c3, Ahi[12], Ahi[13], Ahi[14], Ahi[15], f1.z, f1.w);

                int n0 = tile * 8 + 2 * q;            // dist~ = ||e||^2 - m (A const/pixel)
                float B0 = sBN[n0], B1 = sBN[n0 + 1];
                dL[tt * 2]     = __fsub_rn(B0, c0);
                dL[tt * 2 + 1] = __fsub_rn(B1, c1);
                dH[tt * 2]     = __fsub_rn(B0, c2);
                dH[tt * 2 + 1] = __fsub_rn(B1, c3);
            }
            float mnL = dL[0], mnH = dH[0];
            #pragma unroll
            for (int i = 1; i < 8; i++) { mnL = fminf(mnL, dL[i]); mnH = fminf(mnH, dH[i]); }
            bestL = fminf(bestL, mnL);                // lane-local update only
            bestH = fminf(bestH, mnH);

            float thL = bestL + DELTA, thH = bestH + DELTA;
            #pragma unroll
            for (int tt = 0; tt < 4; tt++) {
                int n0 = (s * 16 + g * 4 + tt) * 8 + 2 * q;
                if (dL[tt * 2] < thL) {
                    int sl = atomicAdd(&sCnt[lpL], 1);
                    if (sl < CAP) sCand[lpL * CAP + sl] = (unsigned short)n0;
                }
                if (dL[tt * 2 + 1] < thL) {
                    int sl = atomicAdd(&sCnt[lpL], 1);
                    if (sl < CAP) sCand[lpL * CAP + sl] = (unsigned short)(n0 + 1);
                }
                if (dH[tt * 2] < thH) {
                    int sl = atomicAdd(&sCnt[lpH], 1);
                    if (sl < CAP) sCand[lpH * CAP + sl] = (unsigned short)n0;
                }
                if (dH[tt * 2 + 1] < thH) {
                    int sl = atomicAdd(&sCnt[lpH], 1);
                    if (sl < CAP) sCand[lpH * CAP + sl] = (unsigned short)(n0 + 1);
                }
            }
        }
        // cross-lane best sharing once per stage (stale-best window stays a superset)
        bestL = fminf(bestL, __shfl_xor_sync(0xFFFFFFFFu, bestL, 1));
        bestL = fminf(bestL, __shfl_xor_sync(0xFFFFFFFFu, bestL, 2));
        bestH = fminf(bestH, __shfl_xor_sync(0xFFFFFFFFu, bestH, 1));
        bestH = fminf(bestH, __shfl_xor_sync(0xFFFFFFFFu, bestH, 2));
        __syncthreads();
    }

    // ---------------- phase B: exact rescore on ALL 256 threads (2 per pixel) ----------------
    __syncthreads();

    int lp   = tid & 127;                             // local pixel
    int half = tid >> 7;                              // 0: even candidates/dims 0-31; 1: odd/32-63
    int p    = p0b + lp;
    int b    = p >> 10;
    int hw   = p & 1023;
    const float* xp = x + (size_t)b * 65536 + hw;

    float xv[EMB_DIM];
    float A = 0.0f;
    #pragma unroll
    for (int d = 0; d < EMB_DIM; d++) {               // identical sequential chain (both halves)
        float v = xp[(size_t)d * 1024];
        xv[d] = v;
        A = __fadd_rn(A, __fmul_rn(v, v));
    }

    int   cnt = sCnt[lp];
    float bd  = 3.4e38f;
    int   bi  = 0;

    if (cnt > CAP) {                                  // overflow: exact full scan, split k-range
        for (int k = half * 512; k < half * 512 + 512; k++) {
            const float* e = w + k * EMB_DIM;
            float m = 0.0f;
            #pragma unroll
            for (int d = 0; d < EMB_DIM; d++) m = __fmaf_rn(xv[d], e[d], m);
            float dist = __fsub_rn(__fadd_rn(A, g_codeS[k]), 2.0f * m);
            if (dist < bd || (dist == bd && k < bi)) { bd = dist; bi = k; }
        }
    } else {
        for (int j = half; j < cnt; j += 2) {         // split candidate list by parity
            int k = sCand[lp * CAP + j];
            const float4* e4 = reinterpret_cast<const float4*>(w + k * EMB_DIM);
            float m = 0.0f;
            #pragma unroll
            for (int d4 = 0; d4 < 16; d4++) {
                float4 ev = e4[d4];
                m = __fmaf_rn(xv[4 * d4],     ev.x, m);
                m = __fmaf_rn(xv[4 * d4 + 1], ev.y, m);
                m = __fmaf_rn(xv[4 * d4 + 2], ev.z, m);
                m = __fmaf_rn(xv[4 * d4 + 3], ev.w, m);
            }
            float dist = __fsub_rn(__fadd_rn(A, g_codeS[k]), 2.0f * m);
            if (dist < bd || (dist == bd && k < bi)) { bd = dist; bi = k; }
        }
    }

    // combine halves lexicographically on (dist, k) == R7 sequential tie-break result
    if (half == 1) { sBd[lp] = bd; sBi[lp] = bi; }
    __syncthreads();
    if (half == 0) {
        float bd2 = sBd[lp];
        int   bi2 = sBi[lp];
        if (bd2 < bd || (bd2 == bd && bi2 < bi)) bi = bi2;
        out[NELEM + 2 + p] = (float)bi;               // idx output
        atomicAdd(&g_counts[bi], 1);
        sBi[lp] = bi;                                 // publish winner
    }
    __syncthreads();
    if (half == 1) bi = sBi[lp];

    // quantize + STE + loss partial: dims half*32 .. half*32+31
    double acc = 0.0;
    {
        const float4* wr = reinterpret_cast<const float4*>(w + bi * EMB_DIM) + half * 8;
        float* ob = out + (size_t)b * 65536 + hw;
        int dbase = half * 32;
        #pragma unroll
        for (int j = 0; j < 8; j++) {
            float4 qv = wr[j];
            int d0i = dbase + 4 * j;
            float x0 = xv[d0i], x1 = xv[d0i + 1], x2 = xv[d0i + 2], x3 = xv[d0i + 3];
            float d0 = __fsub_rn(qv.x, x0), d1 = __fsub_rn(qv.y, x1);
            float d2 = __fsub_rn(qv.z, x2), d3 = __fsub_rn(qv.w, x3);
            ob[(size_t)(d0i)     * 1024] = __fadd_rn(x0, d0);
            ob[(size_t)(d0i + 1) * 1024] = __fadd_rn(x1, d1);
            ob[(size_t)(d0i + 2) * 1024] = __fadd_rn(x2, d2);
            ob[(size_t)(d0i + 3) * 1024] = __fadd_rn(x3, d3);
            acc += (double)d0 * d0 + (double)d1 * d1 + (double)d2 * d2 + (double)d3 * d3;
        }
    }
    __syncthreads();                                  // phase A/B smem reads done before alias

    sd[tid] = acc;
    __syncthreads();
    #pragma unroll
    for (int s = 128; s > 0; s >>= 1) {
        if (tid < s) sd[tid] += sd[tid + s];
        __syncthreads();
    }
    if (tid == 0) g_part[blockIdx.x] = sd[0];
    __threadfence();
    if (tid == 0) isLast = (atomicAdd(&g_ticket, 1) == NBLK - 1);
    __syncthreads();

    if (isLast) {                                     // deterministic final reduction
        __threadfence();
        sd[tid] = g_part[tid * 2] + g_part[tid * 2 + 1];

        float f = 0.0f;
        #pragma unroll
        for (int i = 0; i < NUM_EMB / 256; i++) {
            float pr = (float)g_counts[tid * (NUM_EMB / 256) + i] * (1.0f / 65536.0f);
            f += pr * logf(pr + 1e-10f);
        }
        sf[tid] = f;
        __syncthreads();
        #pragma unroll
        for (int st = 128; st > 0; st >>= 1) {
            if (tid < st) { sd[tid] += sd[tid + st]; sf[tid] += sf[tid + st]; }
            __syncthreads();
        }
        if (tid == 0) {
            float m = (float)(sd[0] / (double)NELEM);
            out[NELEM]     = __fadd_rn(m, __fmul_rn(0.25f, m));  // q_loss + 0.25*e_loss
            out[NELEM + 1] = expf(-sf[0]);
        }
    }
}

extern "C" void kernel_launch(void* const* d_in, const int* in_sizes, int n_in,
                              void* d_out, int out_size) {
    const float* x;
    const float* w;
    if (in_sizes[0] == NELEM) { x = (const float*)d_in[0]; w = (const float*)d_in[1]; }
    else                      { x = (const float*)d_in[1]; w = (const float*)d_in[0]; }
    float* out = (float*)d_out;

    prep_kernel<<<16, 256>>>(w);
    fused_kernel<<<NBLK, 256>>>(x, w, out);
}

// round 13
// speedup vs baseline: 5.5264x; 4.0120x over previous
#include <cuda_runtime.h>
#include <cuda_bf16.h>
#include <cstdint>

#define NUM_EMB 1024
#define EMB_DIM 64
#define NPIX    65536      // 64 * 32 * 32 pixels
#define NELEM   4194304    // 64 * 64 * 32 * 32
#define NBLK    512        // fused-kernel blocks (128 px each)
#define CAP     32         // candidate buffer per pixel
#define DELTA   2e-3f      // screen window >= 2*max_bf16_err + grid slop

// ---------------- device scratch (no allocs allowed) ----------------
__device__ float    g_codeS[NUM_EMB];
__device__ int      g_counts[NUM_EMB];
__device__ double   g_part[NBLK];
__device__ int      g_ticket;
__device__ uint4    g_bfrag[128 * 64];            // [tile][2 groups x 32 lanes] bf16-hi fragments

// ---------------- helpers ----------------
static __device__ __forceinline__ uint32_t packbf(float a, float b) {
    uint16_t ha = __bfloat16_as_ushort(__float2bfloat16_rn(a));
    uint16_t hb = __bfloat16_as_ushort(__float2bfloat16_rn(b));
    return (uint32_t)ha | ((uint32_t)hb << 16);
}
static __device__ __forceinline__ void mma16816(float& c0, float& c1, float& c2, float& c3,
                                                uint32_t a0, uint32_t a1, uint32_t a2, uint32_t a3,
                                                uint32_t b0, uint32_t b1) {
    asm volatile("mma.sync.aligned.m16n8k16.row.col.f32.bf16.bf16.f32 "
                 "{%0,%1,%2,%3}, {%4,%5,%6,%7}, {%8,%9}, {%0,%1,%2,%3};"
                 : "+f"(c0), "+f"(c1), "+f"(c2), "+f"(c3)
                 : "r"(a0), "r"(a1), "r"(a2), "r"(a3), "r"(b0), "r"(b1));
}
static __device__ __forceinline__ uint32_t smem_u32(const void* p) {
    uint32_t a;
    asm("{ .reg .u64 t; cvta.to.shared.u64 t, %1; cvt.u32.u64 %0, t; }" : "=r"(a) : "l"(p));
    return a;
}
static __device__ __forceinline__ void cp16(uint32_t dst, const void* gsrc) {
    asm volatile("cp.async.cg.shared.global [%0], [%1], 16;"
                 :: "r"(dst), "l"(__cvta_generic_to_global(gsrc)) : "memory");
}
#define CP_COMMIT() asm volatile("cp.async.commit_group;" ::: "memory")
#define CP_WAIT0()  asm volatile("cp.async.wait_group 0;" ::: "memory")

// ---------------- kernel 1: staged prep — norms + bf16-hi fragments ----------------
__global__ void __launch_bounds__(256) prep_kernel(const float* __restrict__ w) {
    __shared__ float se[64 * EMB_DIM];               // 16 KB: this block's codebook rows
    int tid = threadIdx.x;
    int k0  = blockIdx.x * 64;

    const float4* src = reinterpret_cast<const float4*>(w + k0 * EMB_DIM);
    float4*       dst = reinterpret_cast<float4*>(se);
    #pragma unroll
    for (int i = 0; i < 4; i++) dst[tid + 256 * i] = src[tid + 256 * i];
    __syncthreads();

    if (tid < 64) {                                  // exact code norms (validated order)
        const float* row = se + tid * EMB_DIM;
        float s = 0.0f;
        #pragma unroll
        for (int d = 0; d < EMB_DIM; d++)
            s = __fadd_rn(s, __fmul_rn(row[d], row[d]));
        g_codeS[k0 + tid]  = s;
        g_counts[k0 + tid] = 0;
    }
    if (blockIdx.x == 0 && tid == 0) g_ticket = 0;

    int tl   = tid >> 5;
    int lane = tid & 31;
    int tile = blockIdx.x * 8 + tl;
    int q    = lane & 3;
    const float* e = se + (tl * 8 + (lane >> 2)) * EMB_DIM;

    uint32_t hiw[8];
    #pragma unroll
    for (int s = 0; s < 4; s++) {
        int ks = 16 * s + 2 * q;
        hiw[2 * s]     = packbf(e[ks],     e[ks + 1]);
        hiw[2 * s + 1] = packbf(e[ks + 8], e[ks + 9]);
    }
    g_bfrag[tile * 64 +      lane] = make_uint4(hiw[0], hiw[1], hiw[2], hiw[3]);
    g_bfrag[tile * 64 + 32 + lane] = make_uint4(hiw[4], hiw[5], hiw[6], hiw[7]);
}

// ---------------- kernel 2: fused screen + exact rescore + quantize + losses ----------------
__global__ void __launch_bounds__(256, 2) fused_kernel(const float* __restrict__ x,
                                                       const float* __restrict__ w,
                                                       float* __restrict__ out) {
    __shared__ float sBN[NUM_EMB];                   // 4 KB
    __shared__ uint4 sB[2][1024];                    // 32 KB, aliased by sd/sf in final
    __shared__ unsigned short sCand[128 * CAP];      // 8 KB
    __shared__ int   sCnt[128];                      // 0.5 KB
    __shared__ float sBd[128];                       // phase-B combine
    __shared__ int   sBi[128];
    __shared__ bool  isLast;

    double* sd = reinterpret_cast<double*>(&sB[0][0]);         // 256 * 8B
    float*  sf = reinterpret_cast<float*>(&sB[0][0]) + 512;    // 256 * 4B

    int tid  = threadIdx.x;
    int warp = tid >> 5;
    int lane = tid & 31;
    int q    = lane & 3;
    int r    = lane >> 2;
    int p0b  = blockIdx.x * 128;

    // ---------------- phase A: HMMA bf16 screen (R7 champion, verbatim) ----------------
    uint32_t sb0 = smem_u32(&sB[0][0]);
    uint32_t sb1 = smem_u32(&sB[1][0]);
    #pragma unroll
    for (int i = 0; i < 4; i++) cp16(sb0 + (tid + 256 * i) * 16, &g_bfrag[tid + 256 * i]);
    CP_COMMIT();

    #pragma unroll
    for (int i = 0; i < 4; i++) sBN[tid + 256 * i] = g_codeS[tid + 256 * i];
    if (tid < 128) sCnt[tid] = 0;

    int p0 = p0b + warp * 16;
    const float* xb = x + (size_t)(p0 >> 10) * 65536 + (p0 & 1023);  // NCHW, dim stride 1024

    uint32_t Ahi[16];
    #pragma unroll
    for (int s = 0; s < 4; s++) {
        int k0 = 16 * s + 2 * q;
        float p00 = 2.0f * xb[(size_t)k0 * 1024 + r];
        float p01 = 2.0f * xb[(size_t)(k0 + 1) * 1024 + r];
        float p10 = 2.0f * xb[(size_t)k0 * 1024 + r + 8];
        float p11 = 2.0f * xb[(size_t)(k0 + 1) * 1024 + r + 8];
        float p20 = 2.0f * xb[(size_t)(k0 + 8) * 1024 + r];
        float p21 = 2.0f * xb[(size_t)(k0 + 9) * 1024 + r];
        float p30 = 2.0f * xb[(size_t)(k0 + 8) * 1024 + r + 8];
        float p31 = 2.0f * xb[(size_t)(k0 + 9) * 1024 + r + 8];
        Ahi[s * 4 + 0] = packbf(p00, p01);
        Ahi[s * 4 + 1] = packbf(p10, p11);
        Ahi[s * 4 + 2] = packbf(p20, p21);
        Ahi[s * 4 + 3] = packbf(p30, p31);
    }

    float bestL = 3.4e38f, bestH = 3.4e38f;
    int lpL = warp * 16 + r;                          // local pixel ids
    int lpH = lpL + 8;

    for (int s = 0; s < 8; s++) {
        CP_WAIT0();
        __syncthreads();
        if (s < 7) {
            uint32_t db = ((s + 1) & 1) ? sb1 : sb0;
            const uint4* gsrc = g_bfrag + (s + 1) * 1024;
            #pragma unroll
            for (int i = 0; i < 4; i++) cp16(db + (tid + 256 * i) * 16, gsrc + tid + 256 * i);
            CP_COMMIT();
        }
        const uint4* cur = sB[s & 1];

        #pragma unroll
        for (int g = 0; g < 4; g++) {                 // 4 tiles per shfl group
            float dL[8], dH[8];
            #pragma unroll
            for (int tt = 0; tt < 4; tt++) {
                int tile = s * 16 + g * 4 + tt;
                int tloc = (g * 4 + tt) * 64;
                uint4 f0 = cur[tloc + lane];
                uint4 f1 = cur[tloc + 32 + lane];

                float c0 = 0.f, c1 = 0.f, c2 = 0.f, c3 = 0.f;
                mma16816(c0, c1, c2, c3, Ahi[0],  Ahi[1],  Ahi[2],  Ahi[3],  f0.x, f0.y);
                mma16816(c0, c1, c2, c3, Ahi[4],  Ahi[5],  Ahi[6],  Ahi[7],  f0.z, f0.w);
                mma16816(c0, c1, c2, c3, Ahi[8],  Ahi[9],  Ahi[10], Ahi[11], f1.x, f1.y);
                mma16816(c0, c1, c2, c3, Ahi[12], Ahi[13], Ahi[14], Ahi[15], f1.z, f1.w);

                int n0 = tile * 8 + 2 * q;            // dist~ = ||e||^2 - m (A const/pixel)
                float B0 = sBN[n0], B1 = sBN[n0 + 1];
                dL[tt * 2]     = __fsub_rn(B0, c0);
                dL[tt * 2 + 1] = __fsub_rn(B1, c1);
                dH[tt * 2]     = __fsub_rn(B0, c2);
                dH[tt * 2 + 1] = __fsub_rn(B1, c3);
            }
            float mnL = dL[0], mnH = dH[0];
            #pragma unroll
            for (int i = 1; i < 8; i++) { mnL = fminf(mnL, dL[i]); mnH = fminf(mnH, dH[i]); }
            bestL = fminf(bestL, mnL);
            bestH = fminf(bestH, mnH);
            bestL = fminf(bestL, __shfl_xor_sync(0xFFFFFFFFu, bestL, 1));
            bestL = fminf(bestL, __shfl_xor_sync(0xFFFFFFFFu, bestL, 2));
            bestH = fminf(bestH, __shfl_xor_sync(0xFFFFFFFFu, bestH, 1));
            bestH = fminf(bestH, __shfl_xor_sync(0xFFFFFFFFu, bestH, 2));

            float thL = bestL + DELTA, thH = bestH + DELTA;
            #pragma unroll
            for (int tt = 0; tt < 4; tt++) {
                int n0 = (s * 16 + g * 4 + tt) * 8 + 2 * q;
                if (dL[tt * 2] < thL) {
                    int sl = atomicAdd(&sCnt[lpL], 1);
                    if (sl < CAP) sCand[lpL * CAP + sl] = (unsigned short)n0;
                }
                if (dL[tt * 2 + 1] < thL) {
                    int sl = atomicAdd(&sCnt[lpL], 1);
                    if (sl < CAP) sCand[lpL * CAP + sl] = (unsigned short)(n0 + 1);
                }
                if (dH[tt * 2] < thH) {
                    int sl = atomicAdd(&sCnt[lpH], 1);
                    if (sl < CAP) sCand[lpH * CAP + sl] = (unsigned short)n0;
                }
                if (dH[tt * 2 + 1] < thH) {
                    int sl = atomicAdd(&sCnt[lpH], 1);
                    if (sl < CAP) sCand[lpH * CAP + sl] = (unsigned short)(n0 + 1);
                }
            }
        }
        __syncthreads();
    }

    // ---------------- phase B: exact rescore on ALL 256 threads (2 per pixel) ----------------
    __syncthreads();

    int lp   = tid & 127;                             // local pixel
    int half = tid >> 7;                              // 0: even candidates/dims 0-31; 1: odd/32-63
    int p    = p0b + lp;
    int b    = p >> 10;
    int hw   = p & 1023;
    const float* xp = x + (size_t)b * 65536 + hw;

    float xv[EMB_DIM];
    float A = 0.0f;
    #pragma unroll
    for (int d = 0; d < EMB_DIM; d++) {               // identical sequential chain (both halves)
        float v = xp[(size_t)d * 1024];
        xv[d] = v;
        A = __fadd_rn(A, __fmul_rn(v, v));
    }

    int   cnt = sCnt[lp];
    float bd  = 3.4e38f;
    int   bi  = 0;

    if (cnt > CAP) {                                  // overflow: exact full scan, split k-range
        for (int k = half * 512; k < half * 512 + 512; k++) {
            const float* e = w + k * EMB_DIM;
            float m = 0.0f;
            #pragma unroll
            for (int d = 0; d < EMB_DIM; d++) m = __fmaf_rn(xv[d], e[d], m);
            float dist = __fsub_rn(__fadd_rn(A, g_codeS[k]), 2.0f * m);
            if (dist < bd || (dist == bd && k < bi)) { bd = dist; bi = k; }
        }
    } else {
        for (int j = half; j < cnt; j += 2) {         // split candidate list by parity
            int k = sCand[lp * CAP + j];
            const float4* e4 = reinterpret_cast<const float4*>(w + k * EMB_DIM);
            float m = 0.0f;
            #pragma unroll
            for (int d4 = 0; d4 < 16; d4++) {
                float4 ev = e4[d4];
                m = __fmaf_rn(xv[4 * d4],     ev.x, m);
                m = __fmaf_rn(xv[4 * d4 + 1], ev.y, m);
                m = __fmaf_rn(xv[4 * d4 + 2], ev.z, m);
                m = __fmaf_rn(xv[4 * d4 + 3], ev.w, m);
            }
            float dist = __fsub_rn(__fadd_rn(A, g_codeS[k]), 2.0f * m);
            if (dist < bd || (dist == bd && k < bi)) { bd = dist; bi = k; }
        }
    }

    // combine halves lexicographically on (dist, k) == sequential tie-break result
    if (half == 1) { sBd[lp] = bd; sBi[lp] = bi; }
    __syncthreads();
    if (half == 0) {
        float bd2 = sBd[lp];
        int   bi2 = sBi[lp];
        if (bd2 < bd || (bd2 == bd && bi2 < bi)) bi = bi2;
        out[NELEM + 2 + p] = (float)bi;               // idx output
        atomicAdd(&g_counts[bi], 1);
        sBi[lp] = bi;                                 // publish winner
    }
    __syncthreads();
    if (half == 1) bi = sBi[lp];

    // quantize + STE + loss partial: dims half*32 .. half*32+31
    double acc = 0.0;
    {
        const float4* wr = reinterpret_cast<const float4*>(w + bi * EMB_DIM) + half * 8;
        float* ob = out + (size_t)b * 65536 + hw;
        int dbase = half * 32;
        #pragma unroll
        for (int j = 0; j < 8; j++) {
            float4 qv = wr[j];
            int d0i = dbase + 4 * j;
            float x0 = xv[d0i], x1 = xv[d0i + 1], x2 = xv[d0i + 2], x3 = xv[d0i + 3];
            float d0 = __fsub_rn(qv.x, x0), d1 = __fsub_rn(qv.y, x1);
            float d2 = __fsub_rn(qv.z, x2), d3 = __fsub_rn(qv.w, x3);
            ob[(size_t)(d0i)     * 1024] = __fadd_rn(x0, d0);
            ob[(size_t)(d0i + 1) * 1024] = __fadd_rn(x1, d1);
            ob[(size_t)(d0i + 2) * 1024] = __fadd_rn(x2, d2);
            ob[(size_t)(d0i + 3) * 1024] = __fadd_rn(x3, d3);
            acc += (double)d0 * d0 + (double)d1 * d1 + (double)d2 * d2 + (double)d3 * d3;
        }
    }
    __syncthreads();                                  // phase A/B smem reads done before alias

    sd[tid] = acc;
    __syncthreads();
    #pragma unroll
    for (int s = 128; s > 0; s >>= 1) {
        if (tid < s) sd[tid] += sd[tid + s];
        __syncthreads();
    }
    if (tid == 0) g_part[blockIdx.x] = sd[0];
    __threadfence();
    if (tid == 0) isLast = (atomicAdd(&g_ticket, 1) == NBLK - 1);
    __syncthreads();

    if (isLast) {                                     // deterministic final reduction
        __threadfence();
        sd[tid] = g_part[tid * 2] + g_part[tid * 2 + 1];

        float f = 0.0f;
        #pragma unroll
        for (int i = 0; i < NUM_EMB / 256; i++) {
            float pr = (float)g_counts[tid * (NUM_EMB / 256) + i] * (1.0f / 65536.0f);
            f += pr * logf(pr + 1e-10f);
        }
        sf[tid] = f;
        __syncthreads();
        #pragma unroll
        for (int st = 128; st > 0; st >>= 1) {
            if (tid < st) { sd[tid] += sd[tid + st]; sf[tid] += sf[tid + st]; }
            __syncthreads();
        }
        if (tid == 0) {
            float m = (float)(sd[0] / (double)NELEM);
            out[NELEM]     = __fadd_rn(m, __fmul_rn(0.25f, m));  // q_loss + 0.25*e_loss
            out[NELEM + 1] = expf(-sf[0]);
        }
    }
}

extern "C" void kernel_launch(void* const* d_in, const int* in_sizes, int n_in,
                              void* d_out, int out_size) {
    const float* x;
    const float* w;
    if (in_sizes[0] == NELEM) { x = (const float*)d_in[0]; w = (const float*)d_in[1]; }
    else                      { x = (const float*)d_in[1]; w = (const float*)d_in[0]; }
    float* out = (float*)d_out;

    prep_kernel<<<16, 256>>>(w);
    fused_kernel<<<NBLK, 256>>>(x, w, out);
}